// round 10
// baseline (speedup 1.0000x reference)
#include <cuda_runtime.h>
#include <stdint.h>
#include <math.h>

// Problem constants
#define BB 8
#define HH 640
#define WW 640
#define NPIX (HH*WW)          // 409600 pixels per sample
#define NF4  (NPIX/4)         // 102400 float4s per sample
#define BPS 74                // blocks per sample -> 8*74 = 592 = 148 SMs * 4
#define NBLK (BB*BPS)         // 592 blocks: exactly one wave at 4 blocks/SM
#define NT 256
#define PFD (2*NT)            // prefetch distance in float4 units

// -------- device scratch: per-block partial rows (plain stores, no init needed) --------
// layout per block: [cls, pos, tot, posc, norm, ang, angc, pad]
__device__ double g_part[NBLK][8];
__device__ unsigned int g_ticket = 0;   // self-resetting; 0 at module load

__device__ __forceinline__ double warp_red(double v) {
    #pragma unroll
    for (int o = 16; o > 0; o >>= 1) v += __shfl_down_sync(0xffffffffu, v, o);
    return v;
}

// fast single-MUFU approximations (rel err ~2^-22, tolerance is 1e-3)
__device__ __forceinline__ float f_sqrt(float x) {
    float r; asm("sqrt.approx.f32 %0, %1;" : "=f"(r) : "f"(x)); return r;
}
__device__ __forceinline__ float f_rcp(float x) {
    float r; asm("rcp.approx.f32 %0, %1;" : "=f"(r) : "f"(x)); return r;
}
__device__ __forceinline__ void pf_l2(const void* p) {
    asm volatile("prefetch.global.L2 [%0];" :: "l"(p));
}

// transformed key: pos pixels -> 0 (sorts last), neg -> bits(pre)+1 (monotone, pre>=0)
__device__ __forceinline__ unsigned key_of(float d1, float dfv, float tm) {
    float diff = d1 - dfv;
    float pre  = diff * diff * tm;
    return (dfv >= 1e-3f) ? 0u : (__float_as_uint(pre) + 1u);
}

#define HBINS 2048

// ---------------- single fused kernel ----------------
__global__ void __launch_bounds__(NT, 4) k_all(
    const float* __restrict__ fy,      // [B,4,H,W]
    const float* __restrict__ tmask,   // [B,H,W] float
    const int*   __restrict__ trm,     // [B,H,W] int
    const float* __restrict__ distf,   // [B,H,W]
    const float* __restrict__ dirf,    // [B,2,H,W]
    const float* __restrict__ wm,      // [B,H,W]
    float* __restrict__ out)
{
    const int s   = blockIdx.x / BPS;
    const int blk = blockIdx.x % BPS;
    const int tid = threadIdx.x;
    const int wid = tid >> 5, lid = tid & 31;

    // balanced variable-length range of float4s for this block
    const int beg = (int)(((long long)blk       * NF4) / BPS);
    const int end = (int)(((long long)(blk + 1) * NF4) / BPS);

    // ======== phase 1: fused elementwise pass ========
    {
        const float4* c0 = (const float4*)(fy + ((size_t)s*4 + 0) * NPIX);
        const float4* c1 = (const float4*)(fy + ((size_t)s*4 + 1) * NPIX);
        const float4* c2 = (const float4*)(fy + ((size_t)s*4 + 2) * NPIX);
        const float4* c3 = (const float4*)(fy + ((size_t)s*4 + 3) * NPIX);
        const float4* gx4p = (const float4*)(dirf + ((size_t)s*2 + 0) * NPIX);
        const float4* gy4p = (const float4*)(dirf + ((size_t)s*2 + 1) * NPIX);
        const float4* tm4p = (const float4*)(tmask + (size_t)s * NPIX);
        const float4* df4p = (const float4*)(distf + (size_t)s * NPIX);
        const float4* wm4p = (const float4*)(wm    + (size_t)s * NPIX);
        const int4*   tr4p = (const int4*)  (trm   + (size_t)s * NPIX);

        float cls_a = 0.f, pos_a = 0.f, tot_a = 0.f, norm_a = 0.f, ang_a = 0.f, angc_a = 0.f;
        int posc = 0;

        for (int i4 = beg + tid; i4 < end; i4 += NT) {
            // prefetch next+1 iteration's lines into L2 (no regs, no scoreboard)
            int ipf = i4 + PFD; if (ipf >= end) ipf = end - 1;
            pf_l2(c0 + ipf);  pf_l2(c1 + ipf);  pf_l2(c2 + ipf);  pf_l2(c3 + ipf);
            pf_l2(gx4p + ipf); pf_l2(gy4p + ipf);
            pf_l2(tm4p + ipf); pf_l2(df4p + ipf); pf_l2(wm4p + ipf); pf_l2(tr4p + ipf);

            float4 p4 = c0[i4], q4 = c1[i4], x4 = c2[i4], y4 = c3[i4];
            float4 g1 = gx4p[i4], g2 = gy4p[i4];
            float4 t4 = tm4p[i4], d4 = df4p[i4], w4 = wm4p[i4];
            int4   r4 = tr4p[i4];

            #pragma unroll
            for (int e = 0; e < 4; e++) {
                float p   = ((const float*)&p4)[e];
                float d1  = ((const float*)&q4)[e];
                float px  = ((const float*)&x4)[e];
                float py  = ((const float*)&y4)[e];
                float gx  = ((const float*)&g1)[e];
                float gy  = ((const float*)&g2)[e];
                float tm  = ((const float*)&t4)[e];
                float dfv = ((const float*)&d4)[e];
                float w   = ((const float*)&w4)[e];
                int   tr  = ((const int*)&r4)[e];
                bool  trp = (tr > 0);

                // cls: masked BCE -- select argument, one fast log
                float pc  = fminf(fmaxf(p, 1e-7f), 1.0f - 1e-7f);
                float arg = trp ? pc : (1.0f - pc);
                cls_a -= __logf(arg) * tm;

                // distance pre-loss: total + positive part (neg = tot - pos later)
                float diff = d1 - dfv;
                float pre  = diff * diff * tm;
                bool  pos  = (dfv >= 1e-3f);
                tot_a += pre;
                pos_a += pos ? pre : 0.0f;
                posc  += pos ? 1 : 0;

                // flux: gt normalize (reference eps; approx sqrt/rcp, err ~2^-22)
                float gl = f_sqrt(gx*gx + gy*gy);
                float ig = f_rcp(gl + 1e-6f);
                float gtx = gx * ig, gty = gy * ig;
                float ex = px - gtx, ey = py - gty;
                norm_a += w * 0.5f * (ex*ex + ey*ey) * tm;

                // angle (branchless): na = pl*ip, nb = gl*ig, pn.gt = ip*(p.gt)
                float amask = (tm > 0.f && trp) ? 1.0f : 0.0f;
                float pl = f_sqrt(px*px + py*py);
                float ip = f_rcp(pl + 1e-6f);
                float dot = px*gtx + py*gty;
                float na_nb = (pl * ip) * (gl * ig);
                float cosv = (ip * dot) * f_rcp(fmaxf(na_nb, 1e-8f));
                ang_a  += amask * (1.0f - cosv);
                angc_a += amask;
            }
        }

        // block reduction -> per-block partial row
        double v0 = warp_red((double)cls_a);
        double v1 = warp_red((double)pos_a);
        double v2 = warp_red((double)tot_a);
        double v3 = warp_red((double)posc);
        double v4 = warp_red((double)norm_a);
        double v5 = warp_red((double)ang_a);
        double v6 = warp_red((double)angc_a);

        __shared__ double sh[8][7];
        if (lid == 0) {
            sh[wid][0]=v0; sh[wid][1]=v1; sh[wid][2]=v2; sh[wid][3]=v3;
            sh[wid][4]=v4; sh[wid][5]=v5; sh[wid][6]=v6;
        }
        __syncthreads();
        if (tid == 0) {
            double t[7] = {0,0,0,0,0,0,0};
            #pragma unroll
            for (int k = 0; k < 8; k++)
                #pragma unroll
                for (int q = 0; q < 7; q++) t[q] += sh[k][q];
            #pragma unroll
            for (int q = 0; q < 7; q++) g_part[blockIdx.x][q] = t[q];
            g_part[blockIdx.x][7] = 0.0;
        }
    }

    // ======== phase 2: last block finalizes ========
    __shared__ bool amLast;
    __threadfence();
    if (tid == 0) {
        unsigned t = atomicAdd(&g_ticket, 1u);
        amLast = (t == (unsigned)(NBLK - 1));
        if (amLast) g_ticket = 0u;           // self-reset for graph replay
    }
    __syncthreads();
    if (!amLast) return;

    // --- finalize (single block) ---
    __shared__ double sGlob[8][4];           // cls, norm, ang, angc per warp
    __shared__ double sPos[BB], sTot[BB], sCnt[BB];
    __shared__ double sPersample[BB];
    __shared__ long long sK[BB];
    __shared__ int   sNeed[BB];
    __shared__ int   sAnyNeed;
    {
        double c = 0, nrm = 0, an = 0, anc = 0;
        for (int i = tid; i < NBLK; i += NT) {
            const double* r = g_part[i];
            c   += r[0];
            nrm += r[4];
            an  += r[5];
            anc += r[6];
        }
        c = warp_red(c); nrm = warp_red(nrm); an = warp_red(an); anc = warp_red(anc);
        if (lid == 0) { sGlob[wid][0]=c; sGlob[wid][1]=nrm; sGlob[wid][2]=an; sGlob[wid][3]=anc; }

        if (wid < BB) {
            double ps = 0, ts = 0, pc = 0;
            for (int i = lid; i < BPS; i += 32) {
                const double* r = g_part[wid * BPS + i];
                ps += r[1]; ts += r[2]; pc += r[3];
            }
            ps = warp_red(ps); ts = warp_red(ts); pc = warp_red(pc);
            if (lid == 0) { sPos[wid] = ps; sTot[wid] = ts; sCnt[wid] = pc; }
        }
        __syncthreads();
    }

    if (tid == 0) sAnyNeed = 0;
    __syncthreads();
    if (tid < BB) {
        int ss = tid;
        long long npos = (long long)(sCnt[ss] + 0.5);
        long long nneg = (long long)NPIX - npos;
        double posi = 0.0, persample = 0.0;
        int need = 0; long long k = 0;
        double negsum_all = sTot[ss] - sPos[ss];
        if (npos > 0) {
            k = 3 * npos; if (nneg < k) k = nneg;
            posi = sPos[ss] / (double)(npos > 1 ? npos : 1);
            if (k <= 0)          persample = posi;
            else if (k == nneg)  persample = posi + negsum_all / (double)k;
            else                 { need = 1; atomicAdd(&sAnyNeed, 1); }
        } else {
            k = 100; need = 1; posi = 0.0; atomicAdd(&sAnyNeed, 1);
        }
        sPersample[ss] = persample;
        sNeed[ss] = need;
        sK[ss] = k;
        sPos[ss] = posi;
    }
    __syncthreads();

    // rare exact top-k path: 3-level radix select (11/11/10 bits), tie-exact
    if (sAnyNeed) {
        __shared__ unsigned sHist[HBINS];
        __shared__ unsigned sPrefix;
        __shared__ long long sKrem;
        __shared__ double sGt[8];
        __shared__ unsigned long long sAb[8];
        for (int ss = 0; ss < BB; ss++) {
            if (!sNeed[ss]) continue;
            const float* ch1 = fy + ((size_t)ss*4 + 1) * NPIX;
            const float* tmp = tmask + (size_t)ss * NPIX;
            const float* dfp = distf + (size_t)ss * NPIX;
            if (tid == 0) { sKrem = sK[ss]; sPrefix = 0u; }
            __syncthreads();

            const int lvBits[3]  = {11, 11, 10};
            const int lvShift[3] = {21, 10, 0};
            int nbDone = 0;
            for (int lv = 0; lv < 3; lv++) {
                for (int i = tid; i < HBINS; i += NT) sHist[i] = 0u;
                __syncthreads();
                unsigned pmask = nbDone ? (0xffffffffu << (32 - nbDone)) : 0u;
                unsigned pref  = sPrefix;
                for (int i = tid; i < NPIX; i += NT) {
                    unsigned u = key_of(__ldg(ch1+i), __ldg(dfp+i), __ldg(tmp+i));
                    if ((u & pmask) == pref)
                        atomicAdd(&sHist[(u >> lvShift[lv]) & ((1u << lvBits[lv]) - 1u)], 1u);
                }
                __syncthreads();
                if (tid == 0) {
                    long long krem = sKrem, above = 0;
                    int nb = (1 << lvBits[lv]), bsel = 0;
                    for (int b = nb - 1; b >= 0; b--) {
                        long long cc = (long long)sHist[b];
                        if (above + cc >= krem) { bsel = b; break; }
                        above += cc;
                    }
                    sKrem = krem - above;
                    sPrefix = sPrefix | ((unsigned)bsel << lvShift[lv]);
                }
                __syncthreads();
                nbDone += lvBits[lv];
            }
            unsigned pivot_u = sPrefix;
            double gt_local = 0.0; unsigned long long ab_local = 0ull;
            for (int i = tid; i < NPIX; i += NT) {
                float d1 = __ldg(ch1+i), dfv = __ldg(dfp+i), t = __ldg(tmp+i);
                float diff = d1 - dfv;
                float pre  = diff * diff * t;
                unsigned u = (dfv >= 1e-3f) ? 0u : (__float_as_uint(pre) + 1u);
                if (u > pivot_u) { gt_local += (double)pre; ab_local++; }
            }
            double gv = warp_red(gt_local);
            double av = warp_red((double)ab_local);
            if (lid == 0) { sGt[wid] = gv; sAb[wid] = (unsigned long long)(av + 0.5); }
            __syncthreads();
            if (tid == 0) {
                double gts = 0; long long above = 0;
                for (int w = 0; w < 8; w++) { gts += sGt[w]; above += (long long)sAb[w]; }
                long long k = sK[ss];
                long long take = k - above;
                float pivotf = __uint_as_float(pivot_u - 1u);
                double negsum = gts + (double)take * (double)pivotf;
                long long kd = k < 1 ? 1 : k;
                sPersample[ss] = sPos[ss] + negsum / (double)kd;
            }
            __syncthreads();
        }
    }

    // combine
    if (tid == 0) {
        double cls = 0, nr = 0, ag = 0, agc = 0;
        for (int w = 0; w < 8; w++) {
            cls += sGlob[w][0]; nr += sGlob[w][1]; ag += sGlob[w][2]; agc += sGlob[w][3];
        }
        double dis = 0;
        for (int ss = 0; ss < BB; ss++) dis += sPersample[ss];
        dis /= (double)BB;
        cls /= (double)BB * (double)NPIX;
        nr  /= (double)BB * (double)HH;       // .sum(-1).mean() over [B,H,W]
        long long ac = (long long)(agc + 0.5); if (ac < 1) ac = 1;
        ag /= (double)ac;
        out[0] = (float)(cls + 3.0 * dis + 0.5 * (nr + ag));
    }
}

// ---------------- launcher: one kernel ----------------
extern "C" void kernel_launch(void* const* d_in, const int* in_sizes, int n_in,
                              void* d_out, int out_size) {
    const float* fy    = (const float*)d_in[0];
    const float* tmask = (const float*)d_in[1];
    const int*   trm   = (const int*)  d_in[2];
    const float* distf = (const float*)d_in[3];
    const float* dirf  = (const float*)d_in[4];
    const float* wm    = (const float*)d_in[5];
    float* out = (float*)d_out;

    k_all<<<NBLK, NT>>>(fy, tmask, trm, distf, dirf, wm, out);
}

// round 11
// speedup vs baseline: 1.1290x; 1.1290x over previous
#include <cuda_runtime.h>
#include <stdint.h>
#include <math.h>

// Problem constants
#define BB 8
#define HH 640
#define WW 640
#define NPIX (HH*WW)          // 409600 pixels per sample
#define NF4  (NPIX/4)         // 102400 float4s per sample
#define BPS 74                // blocks per sample -> 8*74 = 592 = 148 SMs * 4
#define NBLK (BB*BPS)         // 592 blocks: exactly one wave at 4 blocks/SM
#define NT 256

// -------- device scratch: per-block partial rows (plain stores, no init needed) --------
// layout per block: [cls, pos, tot, posc, norm, ang, angc, pad]
__device__ double g_part[NBLK][8];
__device__ unsigned int g_ticket = 0;   // self-resetting; 0 at module load

__device__ __forceinline__ double warp_red(double v) {
    #pragma unroll
    for (int o = 16; o > 0; o >>= 1) v += __shfl_down_sync(0xffffffffu, v, o);
    return v;
}

// fast single-MUFU approximations (rel err ~2^-22, tolerance is 1e-3)
__device__ __forceinline__ float f_sqrt(float x) {
    float r; asm("sqrt.approx.f32 %0, %1;" : "=f"(r) : "f"(x)); return r;
}
__device__ __forceinline__ float f_rcp(float x) {
    float r; asm("rcp.approx.f32 %0, %1;" : "=f"(r) : "f"(x)); return r;
}

// transformed key: pos pixels -> 0 (sorts last), neg -> bits(pre)+1 (monotone, pre>=0)
__device__ __forceinline__ unsigned key_of(float d1, float dfv, float tm) {
    float diff = d1 - dfv;
    float pre  = diff * diff * tm;
    return (dfv >= 1e-3f) ? 0u : (__float_as_uint(pre) + 1u);
}

#define HBINS 2048

// ---------------- single fused kernel ----------------
__global__ void __launch_bounds__(NT, 4) k_all(
    const float* __restrict__ fy,      // [B,4,H,W]
    const float* __restrict__ tmask,   // [B,H,W] float (values 0.0 or 1.0)
    const int*   __restrict__ trm,     // [B,H,W] int
    const float* __restrict__ distf,   // [B,H,W]
    const float* __restrict__ dirf,    // [B,2,H,W]
    const float* __restrict__ wm,      // [B,H,W]
    float* __restrict__ out)
{
    const int s   = blockIdx.x / BPS;
    const int blk = blockIdx.x % BPS;
    const int tid = threadIdx.x;
    const int wid = tid >> 5, lid = tid & 31;

    // balanced variable-length range of float4s for this block
    const int beg = (int)(((long long)blk       * NF4) / BPS);
    const int end = (int)(((long long)(blk + 1) * NF4) / BPS);

    // ======== phase 1: fused elementwise pass ========
    {
        const float4* c0 = (const float4*)(fy + ((size_t)s*4 + 0) * NPIX);
        const float4* c1 = (const float4*)(fy + ((size_t)s*4 + 1) * NPIX);
        const float4* c2 = (const float4*)(fy + ((size_t)s*4 + 2) * NPIX);
        const float4* c3 = (const float4*)(fy + ((size_t)s*4 + 3) * NPIX);
        const float4* gx4p = (const float4*)(dirf + ((size_t)s*2 + 0) * NPIX);
        const float4* gy4p = (const float4*)(dirf + ((size_t)s*2 + 1) * NPIX);
        const float4* tm4p = (const float4*)(tmask + (size_t)s * NPIX);
        const float4* df4p = (const float4*)(distf + (size_t)s * NPIX);
        const float4* wm4p = (const float4*)(wm    + (size_t)s * NPIX);
        const int4*   tr4p = (const int4*)  (trm   + (size_t)s * NPIX);

        float cls_a = 0.f, pos_a = 0.f, tot_a = 0.f, norm_a = 0.f, ang_a = 0.f, angc_a = 0.f;
        int posc = 0;

        for (int i4 = beg + tid; i4 < end; i4 += NT) {
            float4 p4 = c0[i4], q4 = c1[i4], x4 = c2[i4], y4 = c3[i4];
            float4 g1 = gx4p[i4], g2 = gy4p[i4];
            float4 t4 = tm4p[i4], d4 = df4p[i4], w4 = wm4p[i4];
            int4   r4 = tr4p[i4];

            #pragma unroll
            for (int e = 0; e < 4; e++) {
                float p   = ((const float*)&p4)[e];
                float d1  = ((const float*)&q4)[e];
                float px  = ((const float*)&x4)[e];
                float py  = ((const float*)&y4)[e];
                float gx  = ((const float*)&g1)[e];
                float gy  = ((const float*)&g2)[e];
                float tm  = ((const float*)&t4)[e];
                float dfv = ((const float*)&d4)[e];
                float w   = ((const float*)&w4)[e];
                int   tr  = ((const int*)&r4)[e];
                bool  trp = (tr > 0);

                // cls: masked BCE -- select argument, one fast log
                float pc  = fminf(fmaxf(p, 1e-7f), 1.0f - 1e-7f);
                float arg = trp ? pc : (1.0f - pc);
                cls_a -= __logf(arg) * tm;

                // distance pre-loss: total + positive part (neg = tot - pos later)
                float diff = d1 - dfv;
                float pre  = diff * diff * tm;
                bool  pos  = (dfv >= 1e-3f);
                tot_a += pre;
                pos_a += pos ? pre : 0.0f;
                posc  += pos ? 1 : 0;

                // flux: gt normalize (reference eps; approx sqrt/rcp, err ~2^-22)
                float gl = f_sqrt(gx*gx + gy*gy);
                float ig = f_rcp(gl + 1e-6f);
                float gtx = gx * ig, gty = gy * ig;
                float ex = px - gtx, ey = py - gty;
                norm_a += w * (ex*ex + ey*ey) * tm;    // 0.5 factor hoisted to finalize

                // angle: tmask is exactly 0.0/1.0 -> amask = trp ? tm : 0 (single FSEL)
                float amask = trp ? tm : 0.0f;
                float pl = f_sqrt(px*px + py*py);
                float ip = f_rcp(pl + 1e-6f);
                float dot = px*gtx + py*gty;
                float na_nb = (pl * ip) * (gl * ig);
                float cosv = (ip * dot) * f_rcp(fmaxf(na_nb, 1e-8f));
                ang_a  += amask * (1.0f - cosv);
                angc_a += amask;
            }
        }

        // block reduction -> per-block partial row
        double v0 = warp_red((double)cls_a);
        double v1 = warp_red((double)pos_a);
        double v2 = warp_red((double)tot_a);
        double v3 = warp_red((double)posc);
        double v4 = warp_red((double)norm_a);
        double v5 = warp_red((double)ang_a);
        double v6 = warp_red((double)angc_a);

        __shared__ double sh[8][7];
        if (lid == 0) {
            sh[wid][0]=v0; sh[wid][1]=v1; sh[wid][2]=v2; sh[wid][3]=v3;
            sh[wid][4]=v4; sh[wid][5]=v5; sh[wid][6]=v6;
        }
        __syncthreads();
        if (tid == 0) {
            double t[7] = {0,0,0,0,0,0,0};
            #pragma unroll
            for (int k = 0; k < 8; k++)
                #pragma unroll
                for (int q = 0; q < 7; q++) t[q] += sh[k][q];
            #pragma unroll
            for (int q = 0; q < 7; q++) g_part[blockIdx.x][q] = t[q];
            g_part[blockIdx.x][7] = 0.0;
        }
    }

    // ======== phase 2: last block finalizes ========
    __shared__ bool amLast;
    __threadfence();
    if (tid == 0) {
        unsigned t = atomicAdd(&g_ticket, 1u);
        amLast = (t == (unsigned)(NBLK - 1));
        if (amLast) g_ticket = 0u;           // self-reset for graph replay
    }
    __syncthreads();
    if (!amLast) return;

    // --- finalize (single block) ---
    __shared__ double sGlob[8][4];           // cls, norm, ang, angc per warp
    __shared__ double sPos[BB], sTot[BB], sCnt[BB];
    __shared__ double sPersample[BB];
    __shared__ long long sK[BB];
    __shared__ int   sNeed[BB];
    __shared__ int   sAnyNeed;
    {
        double c = 0, nrm = 0, an = 0, anc = 0;
        for (int i = tid; i < NBLK; i += NT) {
            const double* r = g_part[i];
            c   += r[0];
            nrm += r[4];
            an  += r[5];
            anc += r[6];
        }
        c = warp_red(c); nrm = warp_red(nrm); an = warp_red(an); anc = warp_red(anc);
        if (lid == 0) { sGlob[wid][0]=c; sGlob[wid][1]=nrm; sGlob[wid][2]=an; sGlob[wid][3]=anc; }

        if (wid < BB) {
            double ps = 0, ts = 0, pc = 0;
            for (int i = lid; i < BPS; i += 32) {
                const double* r = g_part[wid * BPS + i];
                ps += r[1]; ts += r[2]; pc += r[3];
            }
            ps = warp_red(ps); ts = warp_red(ts); pc = warp_red(pc);
            if (lid == 0) { sPos[wid] = ps; sTot[wid] = ts; sCnt[wid] = pc; }
        }
        __syncthreads();
    }

    if (tid == 0) sAnyNeed = 0;
    __syncthreads();
    if (tid < BB) {
        int ss = tid;
        long long npos = (long long)(sCnt[ss] + 0.5);
        long long nneg = (long long)NPIX - npos;
        double posi = 0.0, persample = 0.0;
        int need = 0; long long k = 0;
        double negsum_all = sTot[ss] - sPos[ss];
        if (npos > 0) {
            k = 3 * npos; if (nneg < k) k = nneg;
            posi = sPos[ss] / (double)(npos > 1 ? npos : 1);
            if (k <= 0)          persample = posi;
            else if (k == nneg)  persample = posi + negsum_all / (double)k;
            else                 { need = 1; atomicAdd(&sAnyNeed, 1); }
        } else {
            k = 100; need = 1; posi = 0.0; atomicAdd(&sAnyNeed, 1);
        }
        sPersample[ss] = persample;
        sNeed[ss] = need;
        sK[ss] = k;
        sPos[ss] = posi;
    }
    __syncthreads();

    // rare exact top-k path: 3-level radix select (11/11/10 bits), tie-exact
    if (sAnyNeed) {
        __shared__ unsigned sHist[HBINS];
        __shared__ unsigned sPrefix;
        __shared__ long long sKrem;
        __shared__ double sGt[8];
        __shared__ unsigned long long sAb[8];
        for (int ss = 0; ss < BB; ss++) {
            if (!sNeed[ss]) continue;
            const float* ch1 = fy + ((size_t)ss*4 + 1) * NPIX;
            const float* tmp = tmask + (size_t)ss * NPIX;
            const float* dfp = distf + (size_t)ss * NPIX;
            if (tid == 0) { sKrem = sK[ss]; sPrefix = 0u; }
            __syncthreads();

            const int lvBits[3]  = {11, 11, 10};
            const int lvShift[3] = {21, 10, 0};
            int nbDone = 0;
            for (int lv = 0; lv < 3; lv++) {
                for (int i = tid; i < HBINS; i += NT) sHist[i] = 0u;
                __syncthreads();
                unsigned pmask = nbDone ? (0xffffffffu << (32 - nbDone)) : 0u;
                unsigned pref  = sPrefix;
                for (int i = tid; i < NPIX; i += NT) {
                    unsigned u = key_of(__ldg(ch1+i), __ldg(dfp+i), __ldg(tmp+i));
                    if ((u & pmask) == pref)
                        atomicAdd(&sHist[(u >> lvShift[lv]) & ((1u << lvBits[lv]) - 1u)], 1u);
                }
                __syncthreads();
                if (tid == 0) {
                    long long krem = sKrem, above = 0;
                    int nb = (1 << lvBits[lv]), bsel = 0;
                    for (int b = nb - 1; b >= 0; b--) {
                        long long cc = (long long)sHist[b];
                        if (above + cc >= krem) { bsel = b; break; }
                        above += cc;
                    }
                    sKrem = krem - above;
                    sPrefix = sPrefix | ((unsigned)bsel << lvShift[lv]);
                }
                __syncthreads();
                nbDone += lvBits[lv];
            }
            unsigned pivot_u = sPrefix;
            double gt_local = 0.0; unsigned long long ab_local = 0ull;
            for (int i = tid; i < NPIX; i += NT) {
                float d1 = __ldg(ch1+i), dfv = __ldg(dfp+i), t = __ldg(tmp+i);
                float diff = d1 - dfv;
                float pre  = diff * diff * t;
                unsigned u = (dfv >= 1e-3f) ? 0u : (__float_as_uint(pre) + 1u);
                if (u > pivot_u) { gt_local += (double)pre; ab_local++; }
            }
            double gv = warp_red(gt_local);
            double av = warp_red((double)ab_local);
            if (lid == 0) { sGt[wid] = gv; sAb[wid] = (unsigned long long)(av + 0.5); }
            __syncthreads();
            if (tid == 0) {
                double gts = 0; long long above = 0;
                for (int w = 0; w < 8; w++) { gts += sGt[w]; above += (long long)sAb[w]; }
                long long k = sK[ss];
                long long take = k - above;
                float pivotf = __uint_as_float(pivot_u - 1u);
                double negsum = gts + (double)take * (double)pivotf;
                long long kd = k < 1 ? 1 : k;
                sPersample[ss] = sPos[ss] + negsum / (double)kd;
            }
            __syncthreads();
        }
    }

    // combine
    if (tid == 0) {
        double cls = 0, nr = 0, ag = 0, agc = 0;
        for (int w = 0; w < 8; w++) {
            cls += sGlob[w][0]; nr += sGlob[w][1]; ag += sGlob[w][2]; agc += sGlob[w][3];
        }
        double dis = 0;
        for (int ss = 0; ss < BB; ss++) dis += sPersample[ss];
        dis /= (double)BB;
        cls /= (double)BB * (double)NPIX;
        nr  = nr * 0.5 / ((double)BB * (double)HH);   // hoisted 0.5; .sum(-1).mean()
        long long ac = (long long)(agc + 0.5); if (ac < 1) ac = 1;
        ag /= (double)ac;
        out[0] = (float)(cls + 3.0 * dis + 0.5 * (nr + ag));
    }
}

// ---------------- launcher: one kernel ----------------
extern "C" void kernel_launch(void* const* d_in, const int* in_sizes, int n_in,
                              void* d_out, int out_size) {
    const float* fy    = (const float*)d_in[0];
    const float* tmask = (const float*)d_in[1];
    const int*   trm   = (const int*)  d_in[2];
    const float* distf = (const float*)d_in[3];
    const float* dirf  = (const float*)d_in[4];
    const float* wm    = (const float*)d_in[5];
    float* out = (float*)d_out;

    k_all<<<NBLK, NT>>>(fy, tmask, trm, distf, dirf, wm, out);
}